// round 9
// baseline (speedup 1.0000x reference)
#include <cuda_runtime.h>
#include <cuda_bf16.h>
#include <cstdint>

#define NP 8192
#define NG 128
#define NGNG (NG * NG)
#define KSPLIT 128
#define KSLICE 64
#define NSPLIT2 8

// smem byte offsets (dynamic, 80KB total -> 2 blocks/SM)
#define A_HI 0
#define A_LO 16384
#define B_T(ch, p) (32768 + ((ch) * 2 + (p)) * 8192)
#define SMEM_TOTAL 81920

__device__ float g_part[KSPLIT * 3 * NGNG];   // [ks][ch][n*128+m]
__device__ float g_p2[3 * NSPLIT2 * NGNG];    // [ch][split][g]

#define SWZ(o) ((o) ^ (((o) >> 3) & 0x70))

__device__ __forceinline__ uint32_t smem_u32(const void* p) {
    uint32_t a;
    asm("{ .reg .u64 t; cvta.to.shared.u64 t, %1; cvt.u32.u64 %0, t; }"
        : "=r"(a) : "l"(p));
    return a;
}
__device__ __forceinline__ void ldsm4(uint32_t& r0, uint32_t& r1,
                                      uint32_t& r2, uint32_t& r3, uint32_t a) {
    asm volatile("ldmatrix.sync.aligned.m8n8.x4.shared.b16 {%0,%1,%2,%3}, [%4];"
                 : "=r"(r0), "=r"(r1), "=r"(r2), "=r"(r3) : "r"(a));
}
__device__ __forceinline__ void mma16816(float* d, const uint32_t* a,
                                         const uint32_t* b) {
    asm volatile(
        "mma.sync.aligned.m16n8k16.row.col.f32.bf16.bf16.f32 "
        "{%0,%1,%2,%3},{%4,%5,%6,%7},{%8,%9},{%0,%1,%2,%3};"
        : "+f"(d[0]), "+f"(d[1]), "+f"(d[2]), "+f"(d[3])
        : "r"(a[0]), "r"(a[1]), "r"(a[2]), "r"(a[3]), "r"(b[0]), "r"(b[1]));
}
__device__ __forceinline__ uint32_t pack_bf16(float a, float b) {
    uint16_t lo = __bfloat16_as_ushort(__float2bfloat16(a));
    uint16_t hi = __bfloat16_as_ushort(__float2bfloat16(b));
    return (uint32_t)lo | ((uint32_t)hi << 16);
}

// ---------------------------------------------------------------------------
// Main: block (ks, nhalf) builds A hi/lo (128m x 64k) + 3-channel B tables
// (64n x 64k), then bf16 hi/lo-split HMMA (3 terms), fp32 accum.
// 80KB smem -> 2 blocks/SM, 32 warps/SM; phases of sibling blocks overlap.
// Warp tile 16x32: warp grid 8m x 2n.
// ---------------------------------------------------------------------------
__global__ void __launch_bounds__(512, 2) main_kernel(
    const float* __restrict__ X, const float* __restrict__ Y) {
    extern __shared__ char smem[];
    uint32_t sb = smem_u32(smem);
    int tid = threadIdx.x, lane = tid & 31, wid = tid >> 5;
    int bx = blockIdx.x;
    int ks = bx >> 1, nh = bx & 1;
    int kbeg = ks * KSLICE;
    int nbase = nh * 64;

    const float GSTEP = 4.0f / 127.0f;
    const float2* Xv = (const float2*)X;
    const float2* Yv = (const float2*)Y;

    // ---- Build A: Ex[m][k] hi/lo, k-pairs packed, SW128 rows (8K exps) ----
    #pragma unroll
    for (int it = 0; it < 8; it++) {
        int idx = it * 512 + tid;            // 4096 items: 128 m x 32 kpairs
        int kp = idx & 31, m = idx >> 5;
        int kk = 2 * kp;
        float2 x0 = Xv[kbeg + kk];
        float2 x1 = Xv[kbeg + kk + 1];
        float gm = fmaf((float)m, GSTEP, -2.0f);
        float d0 = gm - x0.x, d1 = gm - x1.x;
        float e0 = __expf(-0.5f * d0 * d0);
        float e1 = __expf(-0.5f * d1 * d1);
        float h0 = __bfloat162float(__float2bfloat16(e0));
        float h1 = __bfloat162float(__float2bfloat16(e1));
        uint32_t sw = SWZ((uint32_t)(m * 128 + kk * 2));
        *(uint32_t*)(smem + A_HI + sw) = pack_bf16(h0, h1);
        *(uint32_t*)(smem + A_LO + sw) = pack_bf16(e0 - h0, e1 - h1);
    }
    // ---- Build B (this n-half): ey once, 3 channel tables hi/lo (4K exps) --
    #pragma unroll
    for (int it = 0; it < 4; it++) {
        int idx = it * 512 + tid;            // 2048 items: 64 n x 32 kpairs
        int kp = idx & 31, n = idx >> 5;
        int kk = 2 * kp;
        float2 x0 = Xv[kbeg + kk];
        float2 x1 = Xv[kbeg + kk + 1];
        float2 y0 = Yv[kbeg + kk];
        float2 y1 = Yv[kbeg + kk + 1];
        float gn = fmaf((float)(nbase + n), GSTEP, -2.0f);
        float d0 = gn - x0.y, d1 = gn - x1.y;
        float e0 = __expf(-0.5f * d0 * d0);
        float e1 = __expf(-0.5f * d1 * d1);
        uint32_t sw = SWZ((uint32_t)(n * 128 + kk * 2));
        float v0[3] = { e0, e0 * y0.x, e0 * y0.y };
        float v1[3] = { e1, e1 * y1.x, e1 * y1.y };
        #pragma unroll
        for (int c = 0; c < 3; c++) {
            float h0 = __bfloat162float(__float2bfloat16(v0[c]));
            float h1 = __bfloat162float(__float2bfloat16(v1[c]));
            *(uint32_t*)(smem + B_T(c, 0) + sw) = pack_bf16(h0, h1);
            *(uint32_t*)(smem + B_T(c, 1) + sw) = pack_bf16(v0[c] - h0, v1[c] - h1);
        }
    }
    __syncthreads();

    // ---- Warp tiling: 8 m-warps x 2 n-warps; warp tile 16x32 ---------------
    int wm = (wid & 7) * 16, wn = (wid >> 3) * 32;   // wn is local n
    int arow = lane & 15;
    uint32_t acolx = (uint32_t)((lane >> 4) << 4);
    int brow = (lane & 7) + ((lane & 16) ? 8 : 0);
    uint32_t bcolx = (lane & 8) ? 16u : 0u;
    uint32_t axor = (uint32_t)((arow & 7) << 4);
    uint32_t bxor = (uint32_t)((lane & 7) << 4);
    int quad = lane >> 2, tq = lane & 3;

    #pragma unroll 1
    for (int ch = 0; ch < 3; ch++) {
        float acc[4][4];
        #pragma unroll
        for (int j = 0; j < 4; j++)
            #pragma unroll
            for (int c = 0; c < 4; c++) acc[j][c] = 0.0f;

        #pragma unroll
        for (int split = 0; split < 3; split++) {
            uint32_t Aoff = (split == 2) ? A_LO : A_HI;
            uint32_t Boff = B_T(ch, (split == 1) ? 1 : 0);
            uint32_t ab0 = sb + Aoff + (uint32_t)((wm + arow) * 128);
            uint32_t bb0 = sb + Boff + (uint32_t)((wn + brow) * 128);
            uint32_t bb1 = sb + Boff + (uint32_t)((wn + 16 + brow) * 128);

            #pragma unroll
            for (int kstep = 0; kstep < 4; kstep++) {
                uint32_t acol = (uint32_t)(kstep * 32 + acolx) ^ axor;
                uint32_t bcol = (uint32_t)(kstep * 32 + bcolx) ^ bxor;
                uint32_t a0[4], bf[4][2];
                ldsm4(a0[0], a0[1], a0[2], a0[3], ab0 + acol);
                ldsm4(bf[0][0], bf[0][1], bf[1][0], bf[1][1], bb0 + bcol);
                ldsm4(bf[2][0], bf[2][1], bf[3][0], bf[3][1], bb1 + bcol);
                #pragma unroll
                for (int nt = 0; nt < 4; nt++)
                    mma16816(acc[nt], a0, bf[nt]);
            }
        }

        // Epilogue: fp32 partials to g_part[ks][ch][n*128+m]
        float* base = g_part + (ks * 3 + ch) * NGNG;
        #pragma unroll
        for (int nt = 0; nt < 4; nt++) {
            int m = wm + quad;
            int n = nbase + wn + nt * 8 + 2 * tq;
            base[n * NG + m]           = acc[nt][0];
            base[(n + 1) * NG + m]     = acc[nt][1];
            base[n * NG + m + 8]       = acc[nt][2];
            base[(n + 1) * NG + m + 8] = acc[nt][3];
        }
    }
}

// ---------------------------------------------------------------------------
// Reduce stage 1: 131072 threads (8 splits x 16384 g); sums 16 slices x 3 ch.
// ---------------------------------------------------------------------------
__global__ void __launch_bounds__(256) reduce1_kernel() {
    int idx = blockIdx.x * 256 + threadIdx.x;
    int g = idx & (NGNG - 1);
    int s = idx >> 14;
    int b0 = s * (KSPLIT / NSPLIT2);

    float s0 = 0.0f, s1 = 0.0f, s2 = 0.0f;
    const float* p = g_part + b0 * 3 * NGNG + g;
    #pragma unroll 4
    for (int k = 0; k < KSPLIT / NSPLIT2; k++, p += 3 * NGNG) {
        s0 += p[0];
        s1 += p[NGNG];
        s2 += p[2 * NGNG];
    }
    g_p2[(0 * NSPLIT2 + s) * NGNG + g] = s0;
    g_p2[(1 * NSPLIT2 + s) * NGNG + g] = s1;
    g_p2[(2 * NSPLIT2 + s) * NGNG + g] = s2;
}

// ---------------------------------------------------------------------------
// Reduce stage 2: 16384 threads; sum 8 splits per channel, normalize, write.
// ---------------------------------------------------------------------------
__global__ void __launch_bounds__(256) reduce2_kernel(float* __restrict__ out) {
    int g = blockIdx.x * 256 + threadIdx.x;
    float t0 = 0.0f, t1 = 0.0f, t2 = 0.0f;
    #pragma unroll
    for (int s = 0; s < NSPLIT2; s++) {
        t0 += g_p2[(0 * NSPLIT2 + s) * NGNG + g];
        t1 += g_p2[(1 * NSPLIT2 + s) * NGNG + g];
        t2 += g_p2[(2 * NSPLIT2 + s) * NGNG + g];
    }
    float inv = 1.0f / t0;
    out[g]            = t0;
    out[NGNG + g]     = t1 * inv;
    out[2 * NGNG + g] = t2 * inv;
}

extern "C" void kernel_launch(void* const* d_in, const int* in_sizes, int n_in,
                              void* d_out, int out_size) {
    const float* X = (const float*)d_in[0];
    const float* Y = (const float*)d_in[1];
    float* out = (float*)d_out;

    cudaFuncSetAttribute(main_kernel,
                         cudaFuncAttributeMaxDynamicSharedMemorySize, SMEM_TOTAL);
    main_kernel<<<2 * KSPLIT, 512, SMEM_TOTAL>>>(X, Y);
    reduce1_kernel<<<NSPLIT2 * NGNG / 256, 256>>>();
    reduce2_kernel<<<NGNG / 256, 256>>>(out);
}

// round 10
// speedup vs baseline: 1.3790x; 1.3790x over previous
#include <cuda_runtime.h>
#include <cuda_bf16.h>
#include <cstdint>

#define NP 8192
#define NG 128
#define NGNG (NG * NG)
#define KSPLIT 128
#define KSLICE 64
#define NSPLIT2 8

// smem byte offsets (dynamic, 80KB): A hi/lo + 3 channel B-hi tables
#define A_HI 0
#define A_LO 16384
#define B_T(ch) (32768 + (ch) * 16384)
#define SMEM_TOTAL 81920

// Partials in fragment order: [ks][ch][fi], fi = (mt*4+nt)*2048 + tid*4 + c
__device__ float g_part[KSPLIT * 3 * NGNG];
__device__ float g_p2[NSPLIT2 * 3 * NGNG];    // [s][ch][fi]

#define SWZ(o) ((o) ^ (((o) >> 3) & 0x70))

__device__ __forceinline__ uint32_t smem_u32(const void* p) {
    uint32_t a;
    asm("{ .reg .u64 t; cvta.to.shared.u64 t, %1; cvt.u32.u64 %0, t; }"
        : "=r"(a) : "l"(p));
    return a;
}
__device__ __forceinline__ void ldsm4(uint32_t& r0, uint32_t& r1,
                                      uint32_t& r2, uint32_t& r3, uint32_t a) {
    asm volatile("ldmatrix.sync.aligned.m8n8.x4.shared.b16 {%0,%1,%2,%3}, [%4];"
                 : "=r"(r0), "=r"(r1), "=r"(r2), "=r"(r3) : "r"(a));
}
__device__ __forceinline__ void mma16816(float* d, const uint32_t* a,
                                         const uint32_t* b) {
    asm volatile(
        "mma.sync.aligned.m16n8k16.row.col.f32.bf16.bf16.f32 "
        "{%0,%1,%2,%3},{%4,%5,%6,%7},{%8,%9},{%0,%1,%2,%3};"
        : "+f"(d[0]), "+f"(d[1]), "+f"(d[2]), "+f"(d[3])
        : "r"(a[0]), "r"(a[1]), "r"(a[2]), "r"(a[3]), "r"(b[0]), "r"(b[1]));
}
__device__ __forceinline__ uint32_t pack_bf16(float a, float b) {
    uint16_t lo = __bfloat16_as_ushort(__float2bfloat16(a));
    uint16_t hi = __bfloat16_as_ushort(__float2bfloat16(b));
    return (uint32_t)lo | ((uint32_t)hi << 16);
}

// ---------------------------------------------------------------------------
// Main: block ks builds A hi/lo + 3 channel B-hi tables, then per channel
// 2-term split HMMA (ah*bh + al*bh), fp32 accum. Grid 128, 512 threads,
// warp grid 4m x 4n, warp tile 32x32 (R8-verified fragment scheme).
// Epilogue: fragment-order float4 stores (fully coalesced).
// ---------------------------------------------------------------------------
__global__ void __launch_bounds__(512, 1) main_kernel(
    const float* __restrict__ X, const float* __restrict__ Y) {
    extern __shared__ char smem[];
    uint32_t sb = smem_u32(smem);
    int tid = threadIdx.x, lane = tid & 31, wid = tid >> 5;
    int ks = blockIdx.x;
    int kbeg = ks * KSLICE;

    const float GSTEP = 4.0f / 127.0f;
    const float2* Xv = (const float2*)X;
    const float2* Yv = (const float2*)Y;

    // ---- Build A: Ex[m][k] hi/lo, k-pairs packed, SW128 rows --------------
    #pragma unroll
    for (int it = 0; it < 8; it++) {
        int idx = it * 512 + tid;            // 4096 items: 128 m x 32 kpairs
        int kp = idx & 31, m = idx >> 5;
        int kk = 2 * kp;
        float2 x0 = Xv[kbeg + kk];
        float2 x1 = Xv[kbeg + kk + 1];
        float gm = fmaf((float)m, GSTEP, -2.0f);
        float d0 = gm - x0.x, d1 = gm - x1.x;
        float e0 = __expf(-0.5f * d0 * d0);
        float e1 = __expf(-0.5f * d1 * d1);
        float h0 = __bfloat162float(__float2bfloat16(e0));
        float h1 = __bfloat162float(__float2bfloat16(e1));
        uint32_t sw = SWZ((uint32_t)(m * 128 + kk * 2));
        *(uint32_t*)(smem + A_HI + sw) = pack_bf16(h0, h1);
        *(uint32_t*)(smem + A_LO + sw) = pack_bf16(e0 - h0, e1 - h1);
    }
    // ---- Build B: ey once, 3 channel hi tables (no lo needed) -------------
    #pragma unroll
    for (int it = 0; it < 8; it++) {
        int idx = it * 512 + tid;            // 4096 items: 128 n x 32 kpairs
        int kp = idx & 31, n = idx >> 5;
        int kk = 2 * kp;
        float2 x0 = Xv[kbeg + kk];
        float2 x1 = Xv[kbeg + kk + 1];
        float2 y0 = Yv[kbeg + kk];
        float2 y1 = Yv[kbeg + kk + 1];
        float gn = fmaf((float)n, GSTEP, -2.0f);
        float d0 = gn - x0.y, d1 = gn - x1.y;
        float e0 = __expf(-0.5f * d0 * d0);
        float e1 = __expf(-0.5f * d1 * d1);
        uint32_t sw = SWZ((uint32_t)(n * 128 + kk * 2));
        *(uint32_t*)(smem + B_T(0) + sw) = pack_bf16(e0, e1);
        *(uint32_t*)(smem + B_T(1) + sw) = pack_bf16(e0 * y0.x, e1 * y1.x);
        *(uint32_t*)(smem + B_T(2) + sw) = pack_bf16(e0 * y0.y, e1 * y1.y);
    }
    __syncthreads();

    // ---- Warp tiling (R6/R8-verified fragment scheme) ----------------------
    int wm = (wid & 3) * 32, wn = (wid >> 2) * 32;
    int arow = lane & 15;
    uint32_t acolx = (uint32_t)((lane >> 4) << 4);
    int brow = (lane & 7) + ((lane & 16) ? 8 : 0);
    uint32_t bcolx = (lane & 8) ? 16u : 0u;
    uint32_t axor = (uint32_t)((arow & 7) << 4);
    uint32_t bxor = (uint32_t)((lane & 7) << 4);

    uint32_t ah0 = sb + A_HI + (uint32_t)((wm + arow) * 128);
    uint32_t ah1 = ah0 + 16 * 128;
    uint32_t al0 = sb + A_LO + (uint32_t)((wm + arow) * 128);
    uint32_t al1 = al0 + 16 * 128;

    #pragma unroll 1
    for (int ch = 0; ch < 3; ch++) {
        float acc[2][4][4];
        #pragma unroll
        for (int i = 0; i < 2; i++)
            #pragma unroll
            for (int j = 0; j < 4; j++)
                #pragma unroll
                for (int c = 0; c < 4; c++) acc[i][j][c] = 0.0f;

        uint32_t bb0 = sb + B_T(ch) + (uint32_t)((wn + brow) * 128);
        uint32_t bb1 = sb + B_T(ch) + (uint32_t)((wn + 16 + brow) * 128);

        #pragma unroll
        for (int kstep = 0; kstep < 4; kstep++) {
            uint32_t acol = (uint32_t)(kstep * 32 + acolx) ^ axor;
            uint32_t bcol = (uint32_t)(kstep * 32 + bcolx) ^ bxor;
            uint32_t h0[4], h1[4], l0[4], l1[4], bf[4][2];
            ldsm4(h0[0], h0[1], h0[2], h0[3], ah0 + acol);
            ldsm4(h1[0], h1[1], h1[2], h1[3], ah1 + acol);
            ldsm4(l0[0], l0[1], l0[2], l0[3], al0 + acol);
            ldsm4(l1[0], l1[1], l1[2], l1[3], al1 + acol);
            ldsm4(bf[0][0], bf[0][1], bf[1][0], bf[1][1], bb0 + bcol);
            ldsm4(bf[2][0], bf[2][1], bf[3][0], bf[3][1], bb1 + bcol);
            #pragma unroll
            for (int nt = 0; nt < 4; nt++) {
                mma16816(acc[0][nt], h0, bf[nt]);
                mma16816(acc[1][nt], h1, bf[nt]);
                mma16816(acc[0][nt], l0, bf[nt]);
                mma16816(acc[1][nt], l1, bf[nt]);
            }
        }

        // Epilogue: fragment-order, fully coalesced float4 stores
        float* base = g_part + (ks * 3 + ch) * NGNG;
        #pragma unroll
        for (int mt = 0; mt < 2; mt++) {
            #pragma unroll
            for (int nt = 0; nt < 4; nt++) {
                *(float4*)(base + ((mt * 4 + nt) << 11) + tid * 4) =
                    make_float4(acc[mt][nt][0], acc[mt][nt][1],
                                acc[mt][nt][2], acc[mt][nt][3]);
            }
        }
    }
}

// ---------------------------------------------------------------------------
// Reduce stage 1: 1536 blocks x 256 thr; (s, j) sums 16 slices. Linear in fi.
// ---------------------------------------------------------------------------
__global__ void __launch_bounds__(256) reduce1_kernel() {
    int s = blockIdx.x / 192;
    int jb = blockIdx.x % 192;
    int j = jb * 256 + threadIdx.x;          // 0 .. 49151

    float sum = 0.0f;
    const float* p = g_part + (s * 16) * 3 * NGNG + j;
    #pragma unroll 4
    for (int k = 0; k < 16; k++, p += 3 * NGNG) sum += *p;
    g_p2[s * 3 * NGNG + j] = sum;
}

// ---------------------------------------------------------------------------
// Reduce stage 2: 16384 threads; inverse fragment map, sum 8 splits x 3 ch,
// normalize ch1/ch2 by ch0, coalesced writes.
// ---------------------------------------------------------------------------
__global__ void __launch_bounds__(256) reduce2_kernel(float* __restrict__ out) {
    int g = blockIdx.x * 256 + threadIdx.x;  // n*128 + m
    int m = g & 127, n = g >> 7;

    // Inverse of the R8 fragment mapping:
    // m = wm + mt*16 + quad + 8*(c>>1), n = wn + nt*8 + 2*tq + (c&1)
    int wid = (m >> 5) | ((n >> 5) << 2);
    int mt = (m >> 4) & 1;
    int quad = m & 7;
    int c = (((m >> 3) & 1) << 1) | (n & 1);
    int nt = (n >> 3) & 3;
    int tq = (n >> 1) & 3;
    int tidm = wid * 32 + quad * 4 + tq;
    int fi = ((mt * 4 + nt) << 11) + tidm * 4 + c;

    float t[3];
    #pragma unroll
    for (int ch = 0; ch < 3; ch++) {
        int j = ch * NGNG + fi;
        float s = 0.0f;
        #pragma unroll
        for (int sp = 0; sp < NSPLIT2; sp++) s += g_p2[sp * 3 * NGNG + j];
        t[ch] = s;
    }
    float inv = 1.0f / t[0];
    out[g]            = t[0];
    out[NGNG + g]     = t[1] * inv;
    out[2 * NGNG + g] = t[2] * inv;
}

extern "C" void kernel_launch(void* const* d_in, const int* in_sizes, int n_in,
                              void* d_out, int out_size) {
    const float* X = (const float*)d_in[0];
    const float* Y = (const float*)d_in[1];
    float* out = (float*)d_out;

    cudaFuncSetAttribute(main_kernel,
                         cudaFuncAttributeMaxDynamicSharedMemorySize, SMEM_TOTAL);
    main_kernel<<<KSPLIT, 512, SMEM_TOTAL>>>(X, Y);
    reduce1_kernel<<<NSPLIT2 * 192, 256>>>();
    reduce2_kernel<<<NGNG / 256, 256>>>(out);
}

// round 11
// speedup vs baseline: 1.4052x; 1.0190x over previous
#include <cuda_runtime.h>
#include <cuda_bf16.h>
#include <cuda_fp16.h>
#include <cstdint>

#define NP 8192
#define NG 128
#define NGNG (NG * NG)
#define KSPLIT 128
#define KSLICE 64
#define NSPLIT2 8
#define H2_PER_SLICE (3 * NGNG / 2)   // 24576 half2 per slice

// smem byte offsets (dynamic, 80KB): A hi/lo + 3 channel B-hi tables
#define A_HI 0
#define A_LO 16384
#define B_T(ch) (32768 + (ch) * 16384)
#define SMEM_TOTAL 81920

// Partials in fragment order, fp16: [ks][ch][fi/2] (half2), 12 MB
__device__ __half2 g_parth[KSPLIT * H2_PER_SLICE];
// Stage-1 output: [s][ch*8192 + fi/2] as float2, 1.5 MB
__device__ float2 g_p2[NSPLIT2 * H2_PER_SLICE];

#define SWZ(o) ((o) ^ (((o) >> 3) & 0x70))

__device__ __forceinline__ uint32_t smem_u32(const void* p) {
    uint32_t a;
    asm("{ .reg .u64 t; cvta.to.shared.u64 t, %1; cvt.u32.u64 %0, t; }"
        : "=r"(a) : "l"(p));
    return a;
}
__device__ __forceinline__ void ldsm4(uint32_t& r0, uint32_t& r1,
                                      uint32_t& r2, uint32_t& r3, uint32_t a) {
    asm volatile("ldmatrix.sync.aligned.m8n8.x4.shared.b16 {%0,%1,%2,%3}, [%4];"
                 : "=r"(r0), "=r"(r1), "=r"(r2), "=r"(r3) : "r"(a));
}
__device__ __forceinline__ void mma16816(float* d, const uint32_t* a,
                                         const uint32_t* b) {
    asm volatile(
        "mma.sync.aligned.m16n8k16.row.col.f32.bf16.bf16.f32 "
        "{%0,%1,%2,%3},{%4,%5,%6,%7},{%8,%9},{%0,%1,%2,%3};"
        : "+f"(d[0]), "+f"(d[1]), "+f"(d[2]), "+f"(d[3])
        : "r"(a[0]), "r"(a[1]), "r"(a[2]), "r"(a[3]), "r"(b[0]), "r"(b[1]));
}
__device__ __forceinline__ uint32_t pack_bf16(float a, float b) {
    uint16_t lo = __bfloat16_as_ushort(__float2bfloat16(a));
    uint16_t hi = __bfloat16_as_ushort(__float2bfloat16(b));
    return (uint32_t)lo | ((uint32_t)hi << 16);
}

// ---------------------------------------------------------------------------
// Main: block ks builds A hi/lo + 3 channel B-hi tables, then per channel
// 2-term split HMMA (ah*bh + al*bh), fp32 accum. Grid 128, 512 threads,
// warp grid 4m x 4n, warp tile 32x32 (verified fragment scheme).
// Epilogue: fragment-order half2 stores (coalesced STG.64, 12 MB total).
// ---------------------------------------------------------------------------
__global__ void __launch_bounds__(512, 1) main_kernel(
    const float* __restrict__ X, const float* __restrict__ Y) {
    extern __shared__ char smem[];
    uint32_t sb = smem_u32(smem);
    int tid = threadIdx.x, lane = tid & 31, wid = tid >> 5;
    int ks = blockIdx.x;
    int kbeg = ks * KSLICE;

    const float GSTEP = 4.0f / 127.0f;
    const float2* Xv = (const float2*)X;
    const float2* Yv = (const float2*)Y;

    // ---- Build A: Ex[m][k] hi/lo, k-pairs packed, SW128 rows --------------
    #pragma unroll
    for (int it = 0; it < 8; it++) {
        int idx = it * 512 + tid;            // 4096 items: 128 m x 32 kpairs
        int kp = idx & 31, m = idx >> 5;
        int kk = 2 * kp;
        float2 x0 = Xv[kbeg + kk];
        float2 x1 = Xv[kbeg + kk + 1];
        float gm = fmaf((float)m, GSTEP, -2.0f);
        float d0 = gm - x0.x, d1 = gm - x1.x;
        float e0 = __expf(-0.5f * d0 * d0);
        float e1 = __expf(-0.5f * d1 * d1);
        float h0 = __bfloat162float(__float2bfloat16(e0));
        float h1 = __bfloat162float(__float2bfloat16(e1));
        uint32_t sw = SWZ((uint32_t)(m * 128 + kk * 2));
        *(uint32_t*)(smem + A_HI + sw) = pack_bf16(h0, h1);
        *(uint32_t*)(smem + A_LO + sw) = pack_bf16(e0 - h0, e1 - h1);
    }
    // ---- Build B: ey once, 3 channel hi tables -----------------------------
    #pragma unroll
    for (int it = 0; it < 8; it++) {
        int idx = it * 512 + tid;            // 4096 items: 128 n x 32 kpairs
        int kp = idx & 31, n = idx >> 5;
        int kk = 2 * kp;
        float2 x0 = Xv[kbeg + kk];
        float2 x1 = Xv[kbeg + kk + 1];
        float2 y0 = Yv[kbeg + kk];
        float2 y1 = Yv[kbeg + kk + 1];
        float gn = fmaf((float)n, GSTEP, -2.0f);
        float d0 = gn - x0.y, d1 = gn - x1.y;
        float e0 = __expf(-0.5f * d0 * d0);
        float e1 = __expf(-0.5f * d1 * d1);
        uint32_t sw = SWZ((uint32_t)(n * 128 + kk * 2));
        *(uint32_t*)(smem + B_T(0) + sw) = pack_bf16(e0, e1);
        *(uint32_t*)(smem + B_T(1) + sw) = pack_bf16(e0 * y0.x, e1 * y1.x);
        *(uint32_t*)(smem + B_T(2) + sw) = pack_bf16(e0 * y0.y, e1 * y1.y);
    }
    __syncthreads();

    // ---- Warp tiling (verified fragment scheme) ----------------------------
    int wm = (wid & 3) * 32, wn = (wid >> 2) * 32;
    int arow = lane & 15;
    uint32_t acolx = (uint32_t)((lane >> 4) << 4);
    int brow = (lane & 7) + ((lane & 16) ? 8 : 0);
    uint32_t bcolx = (lane & 8) ? 16u : 0u;
    uint32_t axor = (uint32_t)((arow & 7) << 4);
    uint32_t bxor = (uint32_t)((lane & 7) << 4);

    uint32_t ah0 = sb + A_HI + (uint32_t)((wm + arow) * 128);
    uint32_t ah1 = ah0 + 16 * 128;
    uint32_t al0 = sb + A_LO + (uint32_t)((wm + arow) * 128);
    uint32_t al1 = al0 + 16 * 128;

    #pragma unroll 1
    for (int ch = 0; ch < 3; ch++) {
        float acc[2][4][4];
        #pragma unroll
        for (int i = 0; i < 2; i++)
            #pragma unroll
            for (int j = 0; j < 4; j++)
                #pragma unroll
                for (int c = 0; c < 4; c++) acc[i][j][c] = 0.0f;

        uint32_t bb0 = sb + B_T(ch) + (uint32_t)((wn + brow) * 128);
        uint32_t bb1 = sb + B_T(ch) + (uint32_t)((wn + 16 + brow) * 128);

        #pragma unroll
        for (int kstep = 0; kstep < 4; kstep++) {
            uint32_t acol = (uint32_t)(kstep * 32 + acolx) ^ axor;
            uint32_t bcol = (uint32_t)(kstep * 32 + bcolx) ^ bxor;
            uint32_t h0[4], h1[4], l0[4], l1[4], bf[4][2];
            ldsm4(h0[0], h0[1], h0[2], h0[3], ah0 + acol);
            ldsm4(h1[0], h1[1], h1[2], h1[3], ah1 + acol);
            ldsm4(l0[0], l0[1], l0[2], l0[3], al0 + acol);
            ldsm4(l1[0], l1[1], l1[2], l1[3], al1 + acol);
            ldsm4(bf[0][0], bf[0][1], bf[1][0], bf[1][1], bb0 + bcol);
            ldsm4(bf[2][0], bf[2][1], bf[3][0], bf[3][1], bb1 + bcol);
            #pragma unroll
            for (int nt = 0; nt < 4; nt++) {
                mma16816(acc[0][nt], h0, bf[nt]);
                mma16816(acc[1][nt], h1, bf[nt]);
                mma16816(acc[0][nt], l0, bf[nt]);
                mma16816(acc[1][nt], l1, bf[nt]);
            }
        }

        // Epilogue: fragment-order, coalesced half2 stores (STG.64)
        __half2* base = g_parth + (ks * 3 + ch) * (NGNG / 2);
        #pragma unroll
        for (int mt = 0; mt < 2; mt++) {
            #pragma unroll
            for (int nt = 0; nt < 4; nt++) {
                __half2 p01 = __float22half2_rn(
                    make_float2(acc[mt][nt][0], acc[mt][nt][1]));
                __half2 p23 = __float22half2_rn(
                    make_float2(acc[mt][nt][2], acc[mt][nt][3]));
                uint2 pk = make_uint2(*(uint32_t*)&p01, *(uint32_t*)&p23);
                *(uint2*)(base + ((mt * 4 + nt) << 10) + tid * 2) = pk;
            }
        }
    }
}

// ---------------------------------------------------------------------------
// Reduce stage 1: 768 blocks x 256 thr = 196608 threads; thread (s, j) sums
// 16 slices of one half2 lane, fp32 accumulate, float2 out. 12 MB read.
// ---------------------------------------------------------------------------
__global__ void __launch_bounds__(256) reduce1_kernel() {
    int s = blockIdx.x / 96;                 // 0..7
    int jb = blockIdx.x % 96;
    int j = jb * 256 + threadIdx.x;          // 0 .. 24575

    float sx = 0.0f, sy = 0.0f;
    const __half2* p = g_parth + (s * 16) * H2_PER_SLICE + j;
    #pragma unroll 4
    for (int k = 0; k < 16; k++, p += H2_PER_SLICE) {
        float2 v = __half22float2(*p);
        sx += v.x;
        sy += v.y;
    }
    g_p2[s * H2_PER_SLICE + j] = make_float2(sx, sy);
}

// ---------------------------------------------------------------------------
// Reduce stage 2: 16384 threads; inverse fragment map, sum 8 splits x 3 ch,
// normalize ch1/ch2 by ch0, coalesced writes.
// ---------------------------------------------------------------------------
__global__ void __launch_bounds__(256) reduce2_kernel(float* __restrict__ out) {
    int g = blockIdx.x * 256 + threadIdx.x;  // n*128 + m
    int m = g & 127, n = g >> 7;

    // Inverse of the fragment mapping:
    // m = wm + mt*16 + quad + 8*(c>>1), n = wn + nt*8 + 2*tq + (c&1)
    int wid = (m >> 5) | ((n >> 5) << 2);
    int mt = (m >> 4) & 1;
    int quad = m & 7;
    int c = (((m >> 3) & 1) << 1) | (n & 1);
    int nt = (n >> 3) & 3;
    int tq = (n >> 1) & 3;
    int tidm = wid * 32 + quad * 4 + tq;
    int fi = ((mt * 4 + nt) << 11) + tidm * 4 + c;
    int j = fi >> 1;                         // half2 index within channel
    int comp = fi & 1;

    float t[3];
    #pragma unroll
    for (int ch = 0; ch < 3; ch++) {
        int jj = ch * (NGNG / 2) + j;
        float s = 0.0f;
        #pragma unroll
        for (int sp = 0; sp < NSPLIT2; sp++) {
            float2 v = g_p2[sp * H2_PER_SLICE + jj];
            s += comp ? v.y : v.x;
        }
        t[ch] = s;
    }
    float inv = 1.0f / t[0];
    out[g]            = t[0];
    out[NGNG + g]     = t[1] * inv;
    out[2 * NGNG + g] = t[2] * inv;
}

extern "C" void kernel_launch(void* const* d_in, const int* in_sizes, int n_in,
                              void* d_out, int out_size) {
    const float* X = (const float*)d_in[0];
    const float* Y = (const float*)d_in[1];
    float* out = (float*)d_out;

    cudaFuncSetAttribute(main_kernel,
                         cudaFuncAttributeMaxDynamicSharedMemorySize, SMEM_TOTAL);
    main_kernel<<<KSPLIT, 512, SMEM_TOTAL>>>(X, Y);
    reduce1_kernel<<<NSPLIT2 * 96, 256>>>();
    reduce2_kernel<<<NGNG / 256, 256>>>(out);
}